// round 14
// baseline (speedup 1.0000x reference)
#include <cuda_runtime.h>
#include <cuda_bf16.h>
#include <cstdint>

// Problem dims
#define NN 8192      // nodes
#define EE 16384     // edges
#define GG 512       // graphs
#define IND 235      // input dim
#define HD 64        // hidden
#define EDIM 52      // edge feature dim
#define KP 240       // padded K (235 -> 240, 15 k-tiles of 16)
#define JB 3456      // U columns: 3328 (d*64+h) + 64 (c0) + 64 (root)
#define JBP 3584     // padded to 14 blocks of 256
#define MROWS 15040  // IN*H
#define NKT 15       // k-tiles

// ---------------- scratch (device globals; no allocation allowed) ----------
// g_A: [mblk 64][kt 15][k 16][pmA 128]  tf32-rounded, swizzled (see aidx)
// g_B: [nblk 14][kt 15][k 16][pnB 256]  tf32-rounded, swizzled (see bidx)
__device__ float g_A[NN * KP];        // 7.9 MB
__device__ float g_B[JBP * KP];       // 3.4 MB
__device__ float g_U[NN * JB];        // 113 MB  U = X @ B^T (logical)
__device__ float g_agg[NN * HD];      // 2.1 MB
__device__ float g_pool[GG * HD];
__device__ int   g_cnt[GG];

// ---------------- helpers ---------------------------------------------------
__device__ __forceinline__ float to_tf32(float x) {
    unsigned u;
    asm("cvt.rna.tf32.f32 %0, %1;" : "=r"(u) : "f"(x));
    return __uint_as_float(u);
}
// physical index of logical A element (node n, feature i)
__device__ __forceinline__ int aidx(int n, int i) {
    int mblk = n >> 7, ml = n & 127;
    int g8 = ml & 15, w = ml >> 4;                // w in 0..7
    int pm = g8 * 8 + (w ^ (g8 & 4));             // bank swizzle
    return ((mblk * NKT + (i >> 4)) * 16 + (i & 15)) * 128 + pm;
}
// physical index of logical B element (out-col n, feature i)
__device__ __forceinline__ int bidx(int n, int i) {
    int nblk = n >> 8, nl = n & 255;
    int gid = nl & 7, c = nl >> 3;                // c in 0..31
    int pn = gid * 32 + (c ^ (gid * 4));          // bank swizzle
    return ((nblk * NKT + (i >> 4)) * 16 + (i & 15)) * 256 + pn;
}
__device__ __forceinline__ void mma_tf32(float* c,
                                         unsigned a0, unsigned a1, unsigned a2, unsigned a3,
                                         unsigned b0, unsigned b1) {
    asm volatile(
        "mma.sync.aligned.m16n8k8.row.col.f32.tf32.tf32.f32 "
        "{%0,%1,%2,%3}, {%4,%5,%6,%7}, {%8,%9}, {%0,%1,%2,%3};"
        : "+f"(c[0]), "+f"(c[1]), "+f"(c[2]), "+f"(c[3])
        : "r"(a0), "r"(a1), "r"(a2), "r"(a3), "r"(b0), "r"(b1));
}
__device__ __forceinline__ void cp16(unsigned saddr, const float* g) {
    asm volatile("cp.async.cg.shared.global [%0], [%1], 16;"
                 :: "r"(saddr), "l"(g) : "memory");
}

// ---------------- prep: fill g_A, zero scratch + pads, root into g_B -------
__global__ void prep_kernel(const float* __restrict__ x,
                            const float* __restrict__ root) {
    const int NPAD = NN * KP;                    // g_A fill (incl k-pad)
    const int NZ1  = NN * HD;
    const int NZ2  = GG * HD;
    const int NZ3  = GG;
    const int NR   = IND * HD;                   // root cols
    const int NB1  = JB * (KP - IND);            // B k-pad (3456 x 5)
    const int NB2  = (JBP - JB) * KP;            // B row-pad (128 x 240)
    const int total = NPAD + NZ1 + NZ2 + NZ3 + NR + NB1 + NB2;
    for (int idx = blockIdx.x * blockDim.x + threadIdx.x; idx < total;
         idx += gridDim.x * blockDim.x) {
        int t = idx;
        if (t < NPAD) {
            int n = t / KP, i = t - n * KP;
            g_A[aidx(n, i)] = (i < IND) ? to_tf32(x[n * IND + i]) : 0.0f;
            continue;
        }
        t -= NPAD;
        if (t < NZ1) { g_agg[t] = 0.0f; continue; }
        t -= NZ1;
        if (t < NZ2) { g_pool[t] = 0.0f; continue; }
        t -= NZ2;
        if (t < NZ3) { g_cnt[t] = 0; continue; }
        t -= NZ3;
        if (t < NR) {
            int i = t >> 6, h = t & 63;
            g_B[bidx(3392 + h, i)] = to_tf32(root[t]);   // root[i,h]
            continue;
        }
        t -= NR;
        if (t < NB1) {
            int n = t / (KP - IND), i = IND + (t - n * (KP - IND));
            g_B[bidx(n, i)] = 0.0f;
            continue;
        }
        t -= NB1;
        {
            int n = JB + t / KP, i = t - (t / KP) * KP;
            g_B[bidx(n, i)] = 0.0f;
        }
    }
}

// ---------------- build C = W2 @ W1 and c0 into g_B ------------------------
// warp per output row m = (i,h); lane handles d = lane, lane+32
__global__ void buildC_kernel(const float* __restrict__ W1,
                              const float* __restrict__ b1,
                              const float* __restrict__ W2,
                              const float* __restrict__ b2) {
    int m = (blockIdx.x * blockDim.x + threadIdx.x) >> 5;
    int lane = threadIdx.x & 31;
    if (m >= MROWS) return;
    const float* w2row = W2 + m * 128;
    int d0 = lane, d1 = lane + 32;
    float acc0 = 0.f, acc1 = 0.f, accb = 0.f;
#pragma unroll 4
    for (int k = 0; k < 128; ++k) {
        float w2 = __ldg(w2row + k);
        float w1a = __ldg(W1 + k * EDIM + d0);
        float w1b = (d1 < EDIM) ? __ldg(W1 + k * EDIM + d1) : 0.0f;
        acc0 = fmaf(w2, w1a, acc0);
        acc1 = fmaf(w2, w1b, acc1);
        accb = fmaf(w2, __ldg(b1 + k), accb);
    }
    int i = m >> 6, h = m & 63;
    g_B[bidx(d0 * 64 + h, i)] = to_tf32(acc0);
    if (d1 < EDIM) g_B[bidx(d1 * 64 + h, i)] = to_tf32(acc1);
    if (lane == 0) g_B[bidx(3328 + h, i)] = to_tf32(accb + b2[m]);
}

// ---------------- main GEMM: tf32 mma.sync, cp.async double-buffer ---------
// CTA tile 128x256, BK=16, 256 threads (8 warps = 2x4 grid of 64x64 tiles)
#define ATILE 2048   // floats per A k-tile (16*128)
#define BTILE 4096   // floats per B k-tile (16*256)
#define BUFSZ 24576  // bytes per buffer (8KB A + 16KB B)

__global__ void __launch_bounds__(256, 1)
gemm_kernel() {
    __shared__ __align__(16) float smem[2 * (ATILE + BTILE)];

    const int tid  = threadIdx.x;
    const int lane = tid & 31;
    const int warp = tid >> 5;
    const int gid  = lane >> 2;       // 0..7
    const int tig  = lane & 3;        // 0..3
    const int m0   = blockIdx.y * 128;
    const int n0   = blockIdx.x * 256;
    const int wm   = (warp >> 2) * 64;         // 0 or 64
    const int wn   = (warp & 3) * 64;          // 0,64,128,192
    const int wm16 = (warp >> 2) * 4;
    const int wn8  = (warp & 3) * 8;
    const int g4   = gid * 4;

    const unsigned sbase = (unsigned)__cvta_generic_to_shared(smem);
    const float* gAt = g_A + blockIdx.y * (NKT * ATILE);
    const float* gBt = g_B + blockIdx.x * (NKT * BTILE);

    // fragment shared-column bases (bank-conflict-free by construction)
    const int cA0 = gid * 8 + (wm16 ^ (gid & 4));
    const int cA1 = (gid + 8) * 8 + (wm16 ^ (gid & 4));
    const int cB0 = gid * 32 + ((wn8 + 0) ^ g4);
    const int cB1 = gid * 32 + ((wn8 + 4) ^ g4);

    float acc[4][8][4];
#pragma unroll
    for (int mt = 0; mt < 4; ++mt)
#pragma unroll
        for (int nt = 0; nt < 8; ++nt)
#pragma unroll
            for (int i = 0; i < 4; ++i) acc[mt][nt][i] = 0.0f;

    // issue tile 0
    {
        unsigned sA = sbase;
        unsigned sB = sbase + ATILE * 4;
        cp16(sA + tid * 16, gAt + tid * 4);
        cp16(sA + (tid + 256) * 16, gAt + (tid + 256) * 4);
#pragma unroll
        for (int j = 0; j < 4; ++j)
            cp16(sB + (tid + j * 256) * 16, gBt + (tid + j * 256) * 4);
        asm volatile("cp.async.commit_group;" ::: "memory");
    }

#pragma unroll 1
    for (int kt = 0; kt < NKT; ++kt) {
        if (kt < NKT - 1) {
            const int nb = (kt + 1) & 1;
            unsigned sA = sbase + nb * BUFSZ;
            unsigned sB = sA + ATILE * 4;
            const float* ga = gAt + (kt + 1) * ATILE;
            const float* gb = gBt + (kt + 1) * BTILE;
            cp16(sA + tid * 16, ga + tid * 4);
            cp16(sA + (tid + 256) * 16, ga + (tid + 256) * 4);
#pragma unroll
            for (int j = 0; j < 4; ++j)
                cp16(sB + (tid + j * 256) * 16, gb + (tid + j * 256) * 4);
            asm volatile("cp.async.commit_group;" ::: "memory");
            asm volatile("cp.async.wait_group 1;" ::: "memory");
        } else {
            asm volatile("cp.async.wait_group 0;" ::: "memory");
        }
        __syncthreads();

        const float* sA = smem + (kt & 1) * (ATILE + BTILE);
        const float* sB = sA + ATILE;

#pragma unroll
        for (int ks = 0; ks < 2; ++ks) {
            const int kk = ks * 8 + tig;
            const float* ap = sA + kk * 128;
            const float* bp = sB + kk * 256;
            float4 A0 = *(const float4*)(ap + cA0);
            float4 A1 = *(const float4*)(ap + cA1);
            float4 A2 = *(const float4*)(ap + 512 + cA0);
            float4 A3 = *(const float4*)(ap + 512 + cA1);
            float4 B0 = *(const float4*)(bp + cB0);
            float4 B1 = *(const float4*)(bp + cB1);
            float4 B2 = *(const float4*)(bp + 1024 + cB0);
            float4 B3 = *(const float4*)(bp + 1024 + cB1);

            unsigned af[4][4];
            {
                const float* a0 = (const float*)&A0;
                const float* a1 = (const float*)&A1;
                const float* a2 = (const float*)&A2;
                const float* a3 = (const float*)&A3;
#pragma unroll
                for (int mt = 0; mt < 4; ++mt) {
                    af[mt][0] = __float_as_uint(a0[mt]);
                    af[mt][1] = __float_as_uint(a1[mt]);
                    af[mt][2] = __float_as_uint(a2[mt]);
                    af[mt][3] = __float_as_uint(a3[mt]);
                }
            }
            const float* b0lo = (const float*)&B0;
            const float* b0hi = (const float*)&B1;
            const float* b1lo = (const float*)&B2;
            const float* b1hi = (const float*)&B3;
#pragma unroll
            for (int nt = 0; nt < 8; ++nt) {
                unsigned bb0 = __float_as_uint(nt < 4 ? b0lo[nt] : b0hi[nt - 4]);
                unsigned bb1 = __float_as_uint(nt < 4 ? b1lo[nt] : b1hi[nt - 4]);
#pragma unroll
                for (int mt = 0; mt < 4; ++mt)
                    mma_tf32(acc[mt][nt], af[mt][0], af[mt][1], af[mt][2], af[mt][3],
                             bb0, bb1);
            }
        }
        __syncthreads();
    }

    // epilogue: write to logical row-major U (skip padded n-columns)
    if (n0 + wn < JB) {
#pragma unroll
        for (int mt = 0; mt < 4; ++mt) {
            int grow = m0 + wm + mt * 16 + gid;
            float* base = g_U + (size_t)grow * JB + n0 + wn + 2 * tig;
#pragma unroll
            for (int nt = 0; nt < 8; ++nt) {
                float* p = base + nt * 8;
                *(float2*)p            = make_float2(acc[mt][nt][0], acc[mt][nt][1]);
                *(float2*)(p + 8 * JB) = make_float2(acc[mt][nt][2], acc[mt][nt][3]);
            }
        }
    }
}

// ---------------- edge kernel: gather U[src], contract ea, scatter to agg --
__global__ void edge_kernel(const int* __restrict__ ei,
                            const float* __restrict__ ea) {
    int e = (blockIdx.x * blockDim.x + threadIdx.x) >> 5;
    int lane = threadIdx.x & 31;
    if (e >= EE) return;
    int src = ei[e];
    int dst = ei[EE + e];
    const float* urow = g_U + (size_t)src * JB;
    const float* earow = ea + e * EDIM;

    float2 acc = *(const float2*)(urow + 3328 + 2 * lane);  // c0 contribution
#pragma unroll 4
    for (int d = 0; d < EDIM; ++d) {
        float ed = __ldg(earow + d);
        float2 u = *(const float2*)(urow + d * 64 + 2 * lane);
        acc.x = fmaf(ed, u.x, acc.x);
        acc.y = fmaf(ed, u.y, acc.y);
    }
    atomicAdd(&g_agg[dst * 64 + 2 * lane],     acc.x);
    atomicAdd(&g_agg[dst * 64 + 2 * lane + 1], acc.y);
}

// ---------------- node kernel: relu(agg + x@root + b), pool scatter --------
__global__ void node_kernel(const int* __restrict__ batch,
                            const float* __restrict__ conv_b) {
    int n = (blockIdx.x * blockDim.x + threadIdx.x) >> 5;
    int lane = threadIdx.x & 31;
    if (n >= NN) return;
    float2 a  = *(const float2*)&g_agg[n * 64 + 2 * lane];
    float2 xr = *(const float2*)(g_U + (size_t)n * JB + 3392 + 2 * lane);
    float ox = fmaxf(a.x + xr.x + __ldg(conv_b + 2 * lane),     0.0f);
    float oy = fmaxf(a.y + xr.y + __ldg(conv_b + 2 * lane + 1), 0.0f);
    int g = batch[n];
    atomicAdd(&g_pool[g * 64 + 2 * lane],     ox);
    atomicAdd(&g_pool[g * 64 + 2 * lane + 1], oy);
    if (lane == 0) atomicAdd(&g_cnt[g], 1);
}

// ---------------- fused MLP head: block per graph --------------------------
__global__ void mlp_kernel(const float* __restrict__ fw1, const float* __restrict__ fb1,
                           const float* __restrict__ fw2, const float* __restrict__ fb2,
                           const float* __restrict__ fw3, const float* __restrict__ fb3,
                           const float* __restrict__ fw4, const float* __restrict__ fb4,
                           float* __restrict__ out) {
    int g = blockIdx.x;
    int t = threadIdx.x;
    __shared__ float s0[64], s1[128], s2[256], s3[128];

    if (t < 64) {
        float c = fmaxf((float)g_cnt[g], 1.0f);
        s0[t] = g_pool[g * 64 + t] / c;
    }
    __syncthreads();

    if (t < 128) {
        float a = fb1[t];
#pragma unroll 8
        for (int j = 0; j < 64; ++j) a = fmaf(__ldg(fw1 + t * 64 + j), s0[j], a);
        s1[t] = fmaxf(a, 0.0f);
    }
    __syncthreads();

    {
        float a = fb2[t];
#pragma unroll 8
        for (int j = 0; j < 128; ++j) a = fmaf(__ldg(fw2 + t * 128 + j), s1[j], a);
        s2[t] = fmaxf(a, 0.0f);
    }
    __syncthreads();

    if (t < 128) {
        float a = fb3[t];
#pragma unroll 8
        for (int j = 0; j < 256; ++j) a = fmaf(__ldg(fw3 + t * 256 + j), s2[j], a);
        s3[t] = fmaxf(a, 0.0f);
    }
    __syncthreads();

    if (t < 32) {
        float a = 0.0f;
        for (int j = t; j < 128; j += 32) a = fmaf(__ldg(fw4 + j), s3[j], a);
#pragma unroll
        for (int o = 16; o; o >>= 1) a += __shfl_down_sync(0xffffffffu, a, o);
        if (t == 0) out[g] = a + fb4[0];
    }
}

// ---------------- launcher -------------------------------------------------
extern "C" void kernel_launch(void* const* d_in, const int* in_sizes, int n_in,
                              void* d_out, int out_size) {
    const float* x      = (const float*)d_in[0];
    const int*   ei     = (const int*)  d_in[1];
    const float* ea     = (const float*)d_in[2];
    const int*   batch  = (const int*)  d_in[3];
    const float* W1     = (const float*)d_in[4];
    const float* b1     = (const float*)d_in[5];
    const float* W2     = (const float*)d_in[6];
    const float* b2     = (const float*)d_in[7];
    const float* root   = (const float*)d_in[8];
    const float* conv_b = (const float*)d_in[9];
    const float* fw1    = (const float*)d_in[10];
    const float* fb1    = (const float*)d_in[11];
    const float* fw2    = (const float*)d_in[12];
    const float* fb2    = (const float*)d_in[13];
    const float* fw3    = (const float*)d_in[14];
    const float* fb3    = (const float*)d_in[15];
    const float* fw4    = (const float*)d_in[16];
    const float* fb4    = (const float*)d_in[17];
    float* out = (float*)d_out;

    prep_kernel<<<4096, 256>>>(x, root);
    buildC_kernel<<<(MROWS + 7) / 8, 256>>>(W1, b1, W2, b2);
    gemm_kernel<<<dim3(JBP / 256, NN / 128), 256>>>();
    edge_kernel<<<EE / 8, 256>>>(ei, ea);
    node_kernel<<<NN / 8, 256>>>(batch, conv_b);
    mlp_kernel<<<GG, 256>>>(fw1, fb1, fw2, fb2, fw3, fb3, fw4, fb4, out);
}

// round 15
// speedup vs baseline: 1.0031x; 1.0031x over previous
#include <cuda_runtime.h>
#include <cuda_bf16.h>
#include <cstdint>

// Problem dims
#define NN 8192      // nodes
#define EE 16384     // edges
#define GG 512       // graphs
#define IND 235      // input dim
#define HD 64        // hidden
#define EDIM 52      // edge feature dim
#define KP 240       // padded K (235 -> 240, 15 k-tiles of 16)
#define JB 3456      // U columns: 3328 (d*64+h) + 64 (c0) + 64 (root)
#define JBP 3584     // padded to 14 blocks of 256
#define MROWS 15040  // IN*H
#define NKT 15       // k-tiles

// ---------------- scratch (device globals; no allocation allowed) ----------
// g_A: [mblk 64][kt 15][k 16][pmA 128]  tf32-rounded, swizzled (see aidx)
// g_B: [nblk 14][kt 15][k 16][pnB 256]  tf32-rounded, swizzled (see bidx)
__device__ float g_A[NN * KP];        // 7.9 MB
__device__ float g_B[JBP * KP];       // 3.4 MB
__device__ float g_U[NN * JB];        // 113 MB  U = X @ B^T (logical)
__device__ float g_agg[NN * HD];      // 2.1 MB
__device__ float g_pool[GG * HD];
__device__ int   g_cnt[GG];

// ---------------- helpers ---------------------------------------------------
__device__ __forceinline__ float to_tf32(float x) {
    unsigned u;
    asm("cvt.rna.tf32.f32 %0, %1;" : "=r"(u) : "f"(x));
    return __uint_as_float(u);
}
// physical index of logical A element (node n, feature i)
__device__ __forceinline__ int aidx(int n, int i) {
    int mblk = n >> 7, ml = n & 127;
    int g8 = ml & 15, w = ml >> 4;                // w in 0..7
    int pm = g8 * 8 + (w ^ (g8 & 4));             // bank swizzle
    return ((mblk * NKT + (i >> 4)) * 16 + (i & 15)) * 128 + pm;
}
// physical index of logical B element (out-col n, feature i)
__device__ __forceinline__ int bidx(int n, int i) {
    int nblk = n >> 8, nl = n & 255;
    int gid = nl & 7, c = nl >> 3;                // c in 0..31
    int pn = gid * 32 + (c ^ (gid * 4));          // bank swizzle
    return ((nblk * NKT + (i >> 4)) * 16 + (i & 15)) * 256 + pn;
}
__device__ __forceinline__ void mma_tf32(float* c,
                                         unsigned a0, unsigned a1, unsigned a2, unsigned a3,
                                         unsigned b0, unsigned b1) {
    asm volatile(
        "mma.sync.aligned.m16n8k8.row.col.f32.tf32.tf32.f32 "
        "{%0,%1,%2,%3}, {%4,%5,%6,%7}, {%8,%9}, {%0,%1,%2,%3};"
        : "+f"(c[0]), "+f"(c[1]), "+f"(c[2]), "+f"(c[3])
        : "r"(a0), "r"(a1), "r"(a2), "r"(a3), "r"(b0), "r"(b1));
}
__device__ __forceinline__ void cp16(unsigned saddr, const float* g) {
    asm volatile("cp.async.cg.shared.global [%0], [%1], 16;"
                 :: "r"(saddr), "l"(g) : "memory");
}

// ---------------- prep: fill g_A, zero scratch + pads, root into g_B -------
__global__ void prep_kernel(const float* __restrict__ x,
                            const float* __restrict__ root) {
    const int NPAD = NN * KP;                    // g_A fill (incl k-pad)
    const int NZ1  = NN * HD;
    const int NZ2  = GG * HD;
    const int NZ3  = GG;
    const int NR   = IND * HD;                   // root cols
    const int NB1  = JB * (KP - IND);            // B k-pad (3456 x 5)
    const int NB2  = (JBP - JB) * KP;            // B row-pad (128 x 240)
    const int total = NPAD + NZ1 + NZ2 + NZ3 + NR + NB1 + NB2;
    for (int idx = blockIdx.x * blockDim.x + threadIdx.x; idx < total;
         idx += gridDim.x * blockDim.x) {
        int t = idx;
        if (t < NPAD) {
            int n = t / KP, i = t - n * KP;
            g_A[aidx(n, i)] = (i < IND) ? to_tf32(x[n * IND + i]) : 0.0f;
            continue;
        }
        t -= NPAD;
        if (t < NZ1) { g_agg[t] = 0.0f; continue; }
        t -= NZ1;
        if (t < NZ2) { g_pool[t] = 0.0f; continue; }
        t -= NZ2;
        if (t < NZ3) { g_cnt[t] = 0; continue; }
        t -= NZ3;
        if (t < NR) {
            int i = t >> 6, h = t & 63;
            g_B[bidx(3392 + h, i)] = to_tf32(root[t]);   // root[i,h]
            continue;
        }
        t -= NR;
        if (t < NB1) {
            int n = t / (KP - IND), i = IND + (t - n * (KP - IND));
            g_B[bidx(n, i)] = 0.0f;
            continue;
        }
        t -= NB1;
        {
            int n = JB + t / KP, i = t - (t / KP) * KP;
            g_B[bidx(n, i)] = 0.0f;
        }
    }
}

// ---------------- build C = W2 @ W1 and c0 into g_B ------------------------
// warp per output row m = (i,h); lane handles d = lane, lane+32
__global__ void buildC_kernel(const float* __restrict__ W1,
                              const float* __restrict__ b1,
                              const float* __restrict__ W2,
                              const float* __restrict__ b2) {
    int m = (blockIdx.x * blockDim.x + threadIdx.x) >> 5;
    int lane = threadIdx.x & 31;
    if (m >= MROWS) return;
    const float* w2row = W2 + m * 128;
    int d0 = lane, d1 = lane + 32;
    float acc0 = 0.f, acc1 = 0.f, accb = 0.f;
#pragma unroll 4
    for (int k = 0; k < 128; ++k) {
        float w2 = __ldg(w2row + k);
        float w1a = __ldg(W1 + k * EDIM + d0);
        float w1b = (d1 < EDIM) ? __ldg(W1 + k * EDIM + d1) : 0.0f;
        acc0 = fmaf(w2, w1a, acc0);
        acc1 = fmaf(w2, w1b, acc1);
        accb = fmaf(w2, __ldg(b1 + k), accb);
    }
    int i = m >> 6, h = m & 63;
    g_B[bidx(d0 * 64 + h, i)] = to_tf32(acc0);
    if (d1 < EDIM) g_B[bidx(d1 * 64 + h, i)] = to_tf32(acc1);
    if (lane == 0) g_B[bidx(3328 + h, i)] = to_tf32(accb + b2[m]);
}

// ---------------- main GEMM: tf32 mma.sync, cp.async double-buffer ---------
// CTA tile 128x256, BK=16, 256 threads (8 warps = 2x4 grid of 64x64 tiles)
#define ATILE 2048   // floats per A k-tile (16*128)
#define BTILE 4096   // floats per B k-tile (16*256)
#define BUFSZ 24576  // bytes per buffer (8KB A + 16KB B)

__global__ void __launch_bounds__(256, 1)
gemm_kernel() {
    __shared__ __align__(16) float smem[2 * (ATILE + BTILE)];

    const int tid  = threadIdx.x;
    const int lane = tid & 31;
    const int warp = tid >> 5;
    const int gid  = lane >> 2;       // 0..7
    const int tig  = lane & 3;        // 0..3
    const int m0   = blockIdx.y * 128;
    const int n0   = blockIdx.x * 256;
    const int wm   = (warp >> 2) * 64;         // 0 or 64
    const int wn   = (warp & 3) * 64;          // 0,64,128,192
    const int wm16 = (warp >> 2) * 4;
    const int wn8  = (warp & 3) * 8;
    const int g4   = gid * 4;

    const unsigned sbase = (unsigned)__cvta_generic_to_shared(smem);
    const float* gAt = g_A + blockIdx.y * (NKT * ATILE);
    const float* gBt = g_B + blockIdx.x * (NKT * BTILE);

    // fragment shared-column bases (bank-conflict-free by construction)
    const int cA0 = gid * 8 + (wm16 ^ (gid & 4));
    const int cA1 = (gid + 8) * 8 + (wm16 ^ (gid & 4));
    const int cB0 = gid * 32 + ((wn8 + 0) ^ g4);
    const int cB1 = gid * 32 + ((wn8 + 4) ^ g4);

    float acc[4][8][4];
#pragma unroll
    for (int mt = 0; mt < 4; ++mt)
#pragma unroll
        for (int nt = 0; nt < 8; ++nt)
#pragma unroll
            for (int i = 0; i < 4; ++i) acc[mt][nt][i] = 0.0f;

    // issue tile 0
    {
        unsigned sA = sbase;
        unsigned sB = sbase + ATILE * 4;
        cp16(sA + tid * 16, gAt + tid * 4);
        cp16(sA + (tid + 256) * 16, gAt + (tid + 256) * 4);
#pragma unroll
        for (int j = 0; j < 4; ++j)
            cp16(sB + (tid + j * 256) * 16, gBt + (tid + j * 256) * 4);
        asm volatile("cp.async.commit_group;" ::: "memory");
    }

#pragma unroll 1
    for (int kt = 0; kt < NKT; ++kt) {
        if (kt < NKT - 1) {
            const int nb = (kt + 1) & 1;
            unsigned sA = sbase + nb * BUFSZ;
            unsigned sB = sA + ATILE * 4;
            const float* ga = gAt + (kt + 1) * ATILE;
            const float* gb = gBt + (kt + 1) * BTILE;
            cp16(sA + tid * 16, ga + tid * 4);
            cp16(sA + (tid + 256) * 16, ga + (tid + 256) * 4);
#pragma unroll
            for (int j = 0; j < 4; ++j)
                cp16(sB + (tid + j * 256) * 16, gb + (tid + j * 256) * 4);
            asm volatile("cp.async.commit_group;" ::: "memory");
            asm volatile("cp.async.wait_group 1;" ::: "memory");
        } else {
            asm volatile("cp.async.wait_group 0;" ::: "memory");
        }
        __syncthreads();

        const float* sA = smem + (kt & 1) * (ATILE + BTILE);
        const float* sB = sA + ATILE;

#pragma unroll
        for (int ks = 0; ks < 2; ++ks) {
            const int kk = ks * 8 + tig;
            const float* ap = sA + kk * 128;
            const float* bp = sB + kk * 256;
            float4 A0 = *(const float4*)(ap + cA0);
            float4 A1 = *(const float4*)(ap + cA1);
            float4 A2 = *(const float4*)(ap + 512 + cA0);
            float4 A3 = *(const float4*)(ap + 512 + cA1);
            float4 B0 = *(const float4*)(bp + cB0);
            float4 B1 = *(const float4*)(bp + cB1);
            float4 B2 = *(const float4*)(bp + 1024 + cB0);
            float4 B3 = *(const float4*)(bp + 1024 + cB1);

            unsigned af[4][4];
            {
                const float* a0 = (const float*)&A0;
                const float* a1 = (const float*)&A1;
                const float* a2 = (const float*)&A2;
                const float* a3 = (const float*)&A3;
#pragma unroll
                for (int mt = 0; mt < 4; ++mt) {
                    af[mt][0] = __float_as_uint(a0[mt]);
                    af[mt][1] = __float_as_uint(a1[mt]);
                    af[mt][2] = __float_as_uint(a2[mt]);
                    af[mt][3] = __float_as_uint(a3[mt]);
                }
            }
            const float* b0lo = (const float*)&B0;
            const float* b0hi = (const float*)&B1;
            const float* b1lo = (const float*)&B2;
            const float* b1hi = (const float*)&B3;
#pragma unroll
            for (int nt = 0; nt < 8; ++nt) {
                unsigned bb0 = __float_as_uint(nt < 4 ? b0lo[nt] : b0hi[nt - 4]);
                unsigned bb1 = __float_as_uint(nt < 4 ? b1lo[nt] : b1hi[nt - 4]);
#pragma unroll
                for (int mt = 0; mt < 4; ++mt)
                    mma_tf32(acc[mt][nt], af[mt][0], af[mt][1], af[mt][2], af[mt][3],
                             bb0, bb1);
            }
        }
        __syncthreads();
    }

    // epilogue: write to logical row-major U (skip padded n-columns)
    if (n0 + wn < JB) {
#pragma unroll
        for (int mt = 0; mt < 4; ++mt) {
            int grow = m0 + wm + mt * 16 + gid;
            float* base = g_U + (size_t)grow * JB + n0 + wn + 2 * tig;
#pragma unroll
            for (int nt = 0; nt < 8; ++nt) {
                float* p = base + nt * 8;
                *(float2*)p            = make_float2(acc[mt][nt][0], acc[mt][nt][1]);
                *(float2*)(p + 8 * JB) = make_float2(acc[mt][nt][2], acc[mt][nt][3]);
            }
        }
    }
}

// ---------------- edge kernel: gather U[src], contract ea, scatter to agg --
__global__ void edge_kernel(const int* __restrict__ ei,
                            const float* __restrict__ ea) {
    int e = (blockIdx.x * blockDim.x + threadIdx.x) >> 5;
    int lane = threadIdx.x & 31;
    if (e >= EE) return;
    int src = ei[e];
    int dst = ei[EE + e];
    const float* urow = g_U + (size_t)src * JB;
    const float* earow = ea + e * EDIM;

    float2 acc = *(const float2*)(urow + 3328 + 2 * lane);  // c0 contribution
#pragma unroll 4
    for (int d = 0; d < EDIM; ++d) {
        float ed = __ldg(earow + d);
        float2 u = *(const float2*)(urow + d * 64 + 2 * lane);
        acc.x = fmaf(ed, u.x, acc.x);
        acc.y = fmaf(ed, u.y, acc.y);
    }
    atomicAdd(&g_agg[dst * 64 + 2 * lane],     acc.x);
    atomicAdd(&g_agg[dst * 64 + 2 * lane + 1], acc.y);
}

// ---------------- node kernel: relu(agg + x@root + b), pool scatter --------
__global__ void node_kernel(const int* __restrict__ batch,
                            const float* __restrict__ conv_b) {
    int n = (blockIdx.x * blockDim.x + threadIdx.x) >> 5;
    int lane = threadIdx.x & 31;
    if (n >= NN) return;
    float2 a  = *(const float2*)&g_agg[n * 64 + 2 * lane];
    float2 xr = *(const float2*)(g_U + (size_t)n * JB + 3392 + 2 * lane);
    float ox = fmaxf(a.x + xr.x + __ldg(conv_b + 2 * lane),     0.0f);
    float oy = fmaxf(a.y + xr.y + __ldg(conv_b + 2 * lane + 1), 0.0f);
    int g = batch[n];
    atomicAdd(&g_pool[g * 64 + 2 * lane],     ox);
    atomicAdd(&g_pool[g * 64 + 2 * lane + 1], oy);
    if (lane == 0) atomicAdd(&g_cnt[g], 1);
}

// ---------------- fused MLP head: block per graph --------------------------
__global__ void mlp_kernel(const float* __restrict__ fw1, const float* __restrict__ fb1,
                           const float* __restrict__ fw2, const float* __restrict__ fb2,
                           const float* __restrict__ fw3, const float* __restrict__ fb3,
                           const float* __restrict__ fw4, const float* __restrict__ fb4,
                           float* __restrict__ out) {
    int g = blockIdx.x;
    int t = threadIdx.x;
    __shared__ float s0[64], s1[128], s2[256], s3[128];

    if (t < 64) {
        float c = fmaxf((float)g_cnt[g], 1.0f);
        s0[t] = g_pool[g * 64 + t] / c;
    }
    __syncthreads();

    if (t < 128) {
        float a = fb1[t];
#pragma unroll 8
        for (int j = 0; j < 64; ++j) a = fmaf(__ldg(fw1 + t * 64 + j), s0[j], a);
        s1[t] = fmaxf(a, 0.0f);
    }
    __syncthreads();

    {
        float a = fb2[t];
#pragma unroll 8
        for (int j = 0; j < 128; ++j) a = fmaf(__ldg(fw2 + t * 128 + j), s1[j], a);
        s2[t] = fmaxf(a, 0.0f);
    }
    __syncthreads();

    if (t < 128) {
        float a = fb3[t];
#pragma unroll 8
        for (int j = 0; j < 256; ++j) a = fmaf(__ldg(fw3 + t * 256 + j), s2[j], a);
        s3[t] = fmaxf(a, 0.0f);
    }
    __syncthreads();

    if (t < 32) {
        float a = 0.0f;
        for (int j = t; j < 128; j += 32) a = fmaf(__ldg(fw4 + j), s3[j], a);
#pragma unroll
        for (int o = 16; o; o >>= 1) a += __shfl_down_sync(0xffffffffu, a, o);
        if (t == 0) out[g] = a + fb4[0];
    }
}

// ---------------- launcher -------------------------------------------------
extern "C" void kernel_launch(void* const* d_in, const int* in_sizes, int n_in,
                              void* d_out, int out_size) {
    const float* x      = (const float*)d_in[0];
    const int*   ei     = (const int*)  d_in[1];
    const float* ea     = (const float*)d_in[2];
    const int*   batch  = (const int*)  d_in[3];
    const float* W1     = (const float*)d_in[4];
    const float* b1     = (const float*)d_in[5];
    const float* W2     = (const float*)d_in[6];
    const float* b2     = (const float*)d_in[7];
    const float* root   = (const float*)d_in[8];
    const float* conv_b = (const float*)d_in[9];
    const float* fw1    = (const float*)d_in[10];
    const float* fb1    = (const float*)d_in[11];
    const float* fw2    = (const float*)d_in[12];
    const float* fb2    = (const float*)d_in[13];
    const float* fw3    = (const float*)d_in[14];
    const float* fb3    = (const float*)d_in[15];
    const float* fw4    = (const float*)d_in[16];
    const float* fb4    = (const float*)d_in[17];
    float* out = (float*)d_out;

    prep_kernel<<<4096, 256>>>(x, root);
    buildC_kernel<<<(MROWS + 7) / 8, 256>>>(W1, b1, W2, b2);
    gemm_kernel<<<dim3(JBP / 256, NN / 128), 256>>>();
    edge_kernel<<<EE / 8, 256>>>(ei, ea);
    node_kernel<<<NN / 8, 256>>>(batch, conv_b);
    mlp_kernel<<<GG, 256>>>(fw1, fb1, fw2, fb2, fw3, fb3, fw4, fb4, out);
}

// round 16
// speedup vs baseline: 1.3274x; 1.3233x over previous
#include <cuda_runtime.h>
#include <cuda_fp16.h>
#include <cstdint>

// Problem dims
#define NN 8192      // nodes
#define EE 16384     // edges
#define GG 512       // graphs
#define IND 235      // input dim
#define HD 64        // hidden
#define EDIM 52      // edge feature dim
#define KP 240       // padded K (235 -> 240, 15 k-tiles of 16)
#define JB 3456      // U columns: 3328 (d*64+h) + 64 (c0) + 64 (root)
#define JBP 3584     // padded to 14 blocks of 256
#define MROWS 15040  // IN*H
#define NKT 15       // k-tiles

// ---------------- scratch (device globals; no allocation allowed) ----------
// g_A half: [mblk 64][kt 15][2048]  fragment-ordered (see aidx_h)
// g_B half: [nblk 14][kt 15][4096]  fragment-ordered (see bidx_h)
__device__ __half g_A[NN * KP];       // 3.9 MB
__device__ __half g_B[JBP * KP];      // 1.7 MB
__device__ float  g_U[NN * JB];       // 113 MB  U = X @ B^T (logical)
__device__ float  g_agg[NN * HD];     // 2.1 MB
__device__ float  g_pool[GG * HD];
__device__ int    g_cnt[GG];

// ---------------- fragment-layout index helpers ----------------------------
// A element (node n, feature i) -> physical half index.
// Within a (mblk,kt) region of 2048 halves:
//   [wgrp 2][mt 4][lane 32][8 halves], 8 halves = {a0lo,a0hi,a1lo,a1hi,a2lo,a2hi,a3lo,a3hi}
__device__ __forceinline__ int aidx_h(int n, int i) {
    int mblk = n >> 7, ml = n & 127;
    int wgrp = ml >> 6, mlo = ml & 63;
    int mt = mlo >> 4, r16 = mlo & 15;
    int gid = r16 & 7, rhalf = r16 >> 3;
    int kt = i >> 4, kl = i & 15;
    int khalf = kl >> 3, k7 = kl & 7;
    int tig = k7 >> 1, lohi = k7 & 1;
    return ((mblk * NKT + kt) << 11) + (wgrp << 10) + (mt << 8)
         + ((gid * 4 + tig) << 3) + ((khalf * 2 + rhalf) << 1) + lohi;
}
// B element (out-col n, feature i) -> physical half index.
// Within a (nblk,kt) region of 4096 halves:
//   [wgrp 4][chunk 4][lane 32][8 halves], 8 = {b0lo,b0hi,b1lo,b1hi}(nt even),{...}(nt odd)
__device__ __forceinline__ int bidx_h(int n, int i) {
    int nblk = n >> 8, nl = n & 255;
    int wgrp = nl >> 6, n64 = nl & 63;
    int nt = n64 >> 3, gid = n64 & 7;
    int kt = i >> 4, kl = i & 15;
    int khalf = kl >> 3, k7 = kl & 7;
    int tig = k7 >> 1, lohi = k7 & 1;
    return ((nblk * NKT + kt) << 12) + (wgrp << 10) + ((nt >> 1) << 8)
         + ((gid * 4 + tig) << 3) + ((nt & 1) << 2) + (khalf << 1) + lohi;
}
__device__ __forceinline__ void mma_f16(float* c, unsigned a0, unsigned a1,
                                        unsigned a2, unsigned a3,
                                        unsigned b0, unsigned b1) {
    asm volatile(
        "mma.sync.aligned.m16n8k16.row.col.f32.f16.f16.f32 "
        "{%0,%1,%2,%3}, {%4,%5,%6,%7}, {%8,%9}, {%0,%1,%2,%3};"
        : "+f"(c[0]), "+f"(c[1]), "+f"(c[2]), "+f"(c[3])
        : "r"(a0), "r"(a1), "r"(a2), "r"(a3), "r"(b0), "r"(b1));
}
__device__ __forceinline__ void cp16(unsigned saddr, const void* g) {
    asm volatile("cp.async.cg.shared.global [%0], [%1], 16;"
                 :: "r"(saddr), "l"(g) : "memory");
}

// ---------------- prep: fill g_A, zero scratch + pads, root into g_B -------
__global__ void prep_kernel(const float* __restrict__ x,
                            const float* __restrict__ root) {
    const int NPAD = NN * KP;
    const int NZ1  = NN * HD;
    const int NZ2  = GG * HD;
    const int NZ3  = GG;
    const int NR   = IND * HD;
    const int NB1  = JB * (KP - IND);
    const int NB2  = (JBP - JB) * KP;
    const int total = NPAD + NZ1 + NZ2 + NZ3 + NR + NB1 + NB2;
    for (int idx = blockIdx.x * blockDim.x + threadIdx.x; idx < total;
         idx += gridDim.x * blockDim.x) {
        int t = idx;
        if (t < NPAD) {
            int n = t / KP, i = t - n * KP;
            g_A[aidx_h(n, i)] = (i < IND) ? __float2half_rn(x[n * IND + i])
                                          : __float2half_rn(0.0f);
            continue;
        }
        t -= NPAD;
        if (t < NZ1) { g_agg[t] = 0.0f; continue; }
        t -= NZ1;
        if (t < NZ2) { g_pool[t] = 0.0f; continue; }
        t -= NZ2;
        if (t < NZ3) { g_cnt[t] = 0; continue; }
        t -= NZ3;
        if (t < NR) {
            int i = t >> 6, h = t & 63;
            g_B[bidx_h(3392 + h, i)] = __float2half_rn(root[t]);
            continue;
        }
        t -= NR;
        if (t < NB1) {
            int n = t / (KP - IND), i = IND + (t - n * (KP - IND));
            g_B[bidx_h(n, i)] = __float2half_rn(0.0f);
            continue;
        }
        t -= NB1;
        {
            int n = JB + t / KP, i = t - (t / KP) * KP;
            g_B[bidx_h(n, i)] = __float2half_rn(0.0f);
        }
    }
}

// ---------------- build C = W2 @ W1 and c0 into g_B ------------------------
__global__ void buildC_kernel(const float* __restrict__ W1,
                              const float* __restrict__ b1,
                              const float* __restrict__ W2,
                              const float* __restrict__ b2) {
    int m = (blockIdx.x * blockDim.x + threadIdx.x) >> 5;
    int lane = threadIdx.x & 31;
    if (m >= MROWS) return;
    const float* w2row = W2 + m * 128;
    int d0 = lane, d1 = lane + 32;
    float acc0 = 0.f, acc1 = 0.f, accb = 0.f;
#pragma unroll 4
    for (int k = 0; k < 128; ++k) {
        float w2 = __ldg(w2row + k);
        float w1a = __ldg(W1 + k * EDIM + d0);
        float w1b = (d1 < EDIM) ? __ldg(W1 + k * EDIM + d1) : 0.0f;
        acc0 = fmaf(w2, w1a, acc0);
        acc1 = fmaf(w2, w1b, acc1);
        accb = fmaf(w2, __ldg(b1 + k), accb);
    }
    int i = m >> 6, h = m & 63;
    g_B[bidx_h(d0 * 64 + h, i)] = __float2half_rn(acc0);
    if (d1 < EDIM) g_B[bidx_h(d1 * 64 + h, i)] = __float2half_rn(acc1);
    if (lane == 0) g_B[bidx_h(3328 + h, i)] = __float2half_rn(accb + b2[m]);
}

// ---------------- main GEMM: fp16 m16n8k16 mma, cp.async double-buffer -----
// CTA tile 128x256, BK=16, 256 threads (8 warps = 2x4 grid of 64x64 tiles)
#define AT_H 2048    // halves per A k-tile
#define BT_H 4096    // halves per B k-tile
#define BUF_B 12288  // bytes per buffer (4KB A + 8KB B)

__global__ void __launch_bounds__(256, 1)
gemm_kernel() {
    __shared__ __align__(16) __half smem[2 * (AT_H + BT_H)];

    const int tid  = threadIdx.x;
    const int lane = tid & 31;
    const int warp = tid >> 5;
    const int gid  = lane >> 2;
    const int tig  = lane & 3;
    const int m0   = blockIdx.y * 128;
    const int n0   = blockIdx.x * 256;
    const int wgA  = warp >> 2;                // 0..1  (wm = wgA*64)
    const int wgB  = warp & 3;                 // 0..3  (wn = wgB*64)

    const unsigned sbase = (unsigned)__cvta_generic_to_shared(smem);
    const __half* gAt = g_A + (size_t)blockIdx.y * (NKT * AT_H);
    const __half* gBt = g_B + (size_t)blockIdx.x * (NKT * BT_H);

    float acc[4][8][4];
#pragma unroll
    for (int mt = 0; mt < 4; ++mt)
#pragma unroll
        for (int nt = 0; nt < 8; ++nt)
#pragma unroll
            for (int i = 0; i < 4; ++i) acc[mt][nt][i] = 0.0f;

    // issue tile 0
    {
        unsigned sA = sbase;
        unsigned sB = sbase + AT_H * 2;
        cp16(sA + tid * 16, gAt + tid * 8);
        cp16(sB + tid * 16, gBt + tid * 8);
        cp16(sB + (tid + 256) * 16, gBt + (tid + 256) * 8);
        asm volatile("cp.async.commit_group;" ::: "memory");
    }

#pragma unroll 1
    for (int kt = 0; kt < NKT; ++kt) {
        if (kt < NKT - 1) {
            const int nb = (kt + 1) & 1;
            unsigned sA = sbase + nb * BUF_B;
            unsigned sB = sA + AT_H * 2;
            const __half* ga = gAt + (kt + 1) * AT_H;
            const __half* gb = gBt + (kt + 1) * BT_H;
            cp16(sA + tid * 16, ga + tid * 8);
            cp16(sB + tid * 16, gb + tid * 8);
            cp16(sB + (tid + 256) * 16, gb + (tid + 256) * 8);
            asm volatile("cp.async.commit_group;" ::: "memory");
            asm volatile("cp.async.wait_group 1;" ::: "memory");
        } else {
            asm volatile("cp.async.wait_group 0;" ::: "memory");
        }
        __syncthreads();

        const __half* sA = smem + (kt & 1) * (AT_H + BT_H);
        const __half* sB = sA + AT_H;

        uint4 Af[4], Bf[4];
#pragma unroll
        for (int mt = 0; mt < 4; ++mt)
            Af[mt] = *(const uint4*)(sA + (wgA << 10) + (mt << 8) + lane * 8);
#pragma unroll
        for (int c = 0; c < 4; ++c)
            Bf[c] = *(const uint4*)(sB + (wgB << 10) + (c << 8) + lane * 8);

#pragma unroll
        for (int c = 0; c < 4; ++c) {
#pragma unroll
            for (int mt = 0; mt < 4; ++mt)
                mma_f16(acc[mt][2 * c], Af[mt].x, Af[mt].y, Af[mt].z, Af[mt].w,
                        Bf[c].x, Bf[c].y);
#pragma unroll
            for (int mt = 0; mt < 4; ++mt)
                mma_f16(acc[mt][2 * c + 1], Af[mt].x, Af[mt].y, Af[mt].z, Af[mt].w,
                        Bf[c].z, Bf[c].w);
        }
        __syncthreads();
    }

    // epilogue: write logical row-major U (skip padded n-columns)
    const int wn = wgB * 64;
    if (n0 + wn < JB) {
#pragma unroll
        for (int mt = 0; mt < 4; ++mt) {
            int grow = m0 + wgA * 64 + mt * 16 + gid;
            float* base = g_U + (size_t)grow * JB + n0 + wn + 2 * tig;
#pragma unroll
            for (int nt = 0; nt < 8; ++nt) {
                float* p = base + nt * 8;
                *(float2*)p            = make_float2(acc[mt][nt][0], acc[mt][nt][1]);
                *(float2*)(p + 8 * JB) = make_float2(acc[mt][nt][2], acc[mt][nt][3]);
            }
        }
    }
}

// ---------------- edge kernel: gather U[src], contract ea, scatter to agg --
__global__ void edge_kernel(const int* __restrict__ ei,
                            const float* __restrict__ ea) {
    int e = (blockIdx.x * blockDim.x + threadIdx.x) >> 5;
    int lane = threadIdx.x & 31;
    if (e >= EE) return;
    int src = ei[e];
    int dst = ei[EE + e];
    const float* urow = g_U + (size_t)src * JB;
    const float* earow = ea + e * EDIM;

    float2 acc = *(const float2*)(urow + 3328 + 2 * lane);  // c0 contribution
#pragma unroll 4
    for (int d = 0; d < EDIM; ++d) {
        float ed = __ldg(earow + d);
        float2 u = *(const float2*)(urow + d * 64 + 2 * lane);
        acc.x = fmaf(ed, u.x, acc.x);
        acc.y = fmaf(ed, u.y, acc.y);
    }
    atomicAdd(&g_agg[dst * 64 + 2 * lane],     acc.x);
    atomicAdd(&g_agg[dst * 64 + 2 * lane + 1], acc.y);
}

// ---------------- node kernel: relu(agg + x@root + b), pool scatter --------
__global__ void node_kernel(const int* __restrict__ batch,
                            const float* __restrict__ conv_b) {
    int n = (blockIdx.x * blockDim.x + threadIdx.x) >> 5;
    int lane = threadIdx.x & 31;
    if (n >= NN) return;
    float2 a  = *(const float2*)&g_agg[n * 64 + 2 * lane];
    float2 xr = *(const float2*)(g_U + (size_t)n * JB + 3392 + 2 * lane);
    float ox = fmaxf(a.x + xr.x + __ldg(conv_b + 2 * lane),     0.0f);
    float oy = fmaxf(a.y + xr.y + __ldg(conv_b + 2 * lane + 1), 0.0f);
    int g = batch[n];
    atomicAdd(&g_pool[g * 64 + 2 * lane],     ox);
    atomicAdd(&g_pool[g * 64 + 2 * lane + 1], oy);
    if (lane == 0) atomicAdd(&g_cnt[g], 1);
}

// ---------------- fused MLP head: block per graph --------------------------
__global__ void mlp_kernel(const float* __restrict__ fw1, const float* __restrict__ fb1,
                           const float* __restrict__ fw2, const float* __restrict__ fb2,
                           const float* __restrict__ fw3, const float* __restrict__ fb3,
                           const float* __restrict__ fw4, const float* __restrict__ fb4,
                           float* __restrict__ out) {
    int g = blockIdx.x;
    int t = threadIdx.x;
    __shared__ float s0[64], s1[128], s2[256], s3[128];

    if (t < 64) {
        float c = fmaxf((float)g_cnt[g], 1.0f);
        s0[t] = g_pool[g * 64 + t] / c;
    }
    __syncthreads();

    if (t < 128) {
        float a = fb1[t];
#pragma unroll 8
        for (int j = 0; j < 64; ++j) a = fmaf(__ldg(fw1 + t * 64 + j), s0[j], a);
        s1[t] = fmaxf(a, 0.0f);
    }
    __syncthreads();

    {
        float a = fb2[t];
#pragma unroll 8
        for (int j = 0; j < 128; ++j) a = fmaf(__ldg(fw2 + t * 128 + j), s1[j], a);
        s2[t] = fmaxf(a, 0.0f);
    }
    __syncthreads();

    if (t < 128) {
        float a = fb3[t];
#pragma unroll 8
        for (int j = 0; j < 256; ++j) a = fmaf(__ldg(fw3 + t * 256 + j), s2[j], a);
        s3[t] = fmaxf(a, 0.0f);
    }
    __syncthreads();

    if (t < 32) {
        float a = 0.0f;
        for (int j = t; j < 128; j += 32) a = fmaf(__ldg(fw4 + j), s3[j], a);
#pragma unroll
        for (int o = 16; o; o >>= 1) a += __shfl_down_sync(0xffffffffu, a, o);
        if (t == 0) out[g] = a + fb4[0];
    }
}

// ---------------- launcher -------------------------------------------------
extern "C" void kernel_launch(void* const* d_in, const int* in_sizes, int n_in,
                              void* d_out, int out_size) {
    const float* x      = (const float*)d_in[0];
    const int*   ei     = (const int*)  d_in[1];
    const float* ea     = (const float*)d_in[2];
    const int*   batch  = (const int*)  d_in[3];
    const float* W1     = (const float*)d_in[4];
    const float* b1     = (const float*)d_in[5];
    const float* W2     = (const float*)d_in[6];
    const float* b2     = (const float*)d_in[7];
    const float* root   = (const float*)d_in[8];
    const float* conv_b = (const float*)d_in[9];
    const float* fw1    = (const float*)d_in[10];
    const float* fb1    = (const float*)d_in[11];
    const float* fw2    = (const float*)d_in[12];
    const float* fb2    = (const float*)d_in[13];
    const float* fw3    = (const float*)d_in[14];
    const float* fb3    = (const float*)d_in[15];
    const float* fw4    = (const float*)d_in[16];
    const float* fb4    = (const float*)d_in[17];
    float* out = (float*)d_out;

    prep_kernel<<<4096, 256>>>(x, root);
    buildC_kernel<<<(MROWS + 7) / 8, 256>>>(W1, b1, W2, b2);
    gemm_kernel<<<dim3(JBP / 256, NN / 128), 256>>>();
    edge_kernel<<<EE / 8, 256>>>(ei, ea);
    node_kernel<<<NN / 8, 256>>>(batch, conv_b);
    mlp_kernel<<<GG, 256>>>(fw1, fb1, fw2, fb2, fw3, fb3, fw4, fb4, out);
}